// round 1
// baseline (speedup 1.0000x reference)
#include <cuda_runtime.h>
#include <cuda_bf16.h>
#include <mma.h>
#include <cstdint>

using namespace nvcuda;

// Problem constants (B=4, S=2048, H=1024, E=8, TOP_K=2)
#define NE    8
#define NTOK  8192
#define HDIM  1024
#define EPSI  1e-10f

// GEMM tiling
#define BM 64
#define BN 64
#define BK 32
#define A_ST 40   // BK + 8 pad (elements) -> 80B row stride, 16B aligned
#define B_ST 72   // BN + 8 pad (elements) -> 144B row stride, 16B aligned

#define NTILE (HDIM / BN)                                  // 16
#define MAX_TILES (((NTOK * 2) / BM + NE) * NTILE)         // (256+8)*16 = 4224

// ---------------- device scratch (static, allocation-free) ----------------
__device__ int   g_counts[NE];
__device__ int   g_tok[NE * NTOK];
__device__ float g_coef[NE * NTOK];

__global__ void zero_counts_kernel() {
    if (threadIdx.x < NE) g_counts[threadIdx.x] = 0;
}

// ---------------- router: logits -> softmax -> top2 -> gather lists -------
__global__ void router_kernel(const float* __restrict__ tokens,
                              const float* __restrict__ rw,
                              const float* __restrict__ rb) {
    __shared__ float sw[NE * HDIM];   // 32 KB: router weights
    int tid = threadIdx.x;
    for (int i = tid; i < NE * HDIM; i += blockDim.x) sw[i] = rw[i];
    __syncthreads();

    int warp  = tid >> 5;
    int lane  = tid & 31;
    int token = blockIdx.x * (blockDim.x >> 5) + warp;
    if (token >= NTOK) return;

    const float* x = tokens + (size_t)token * HDIM;
    float acc[NE];
#pragma unroll
    for (int e = 0; e < NE; e++) acc[e] = 0.f;

    for (int i = lane; i < HDIM; i += 32) {
        float xv = x[i];
#pragma unroll
        for (int e = 0; e < NE; e++) acc[e] += xv * sw[e * HDIM + i];
    }
#pragma unroll
    for (int off = 16; off > 0; off >>= 1) {
#pragma unroll
        for (int e = 0; e < NE; e++)
            acc[e] += __shfl_xor_sync(0xffffffffu, acc[e], off);
    }

    if (lane == 0) {
        float logit[NE];
#pragma unroll
        for (int e = 0; e < NE; e++) logit[e] = acc[e] + rb[e];
        float mx = logit[0];
#pragma unroll
        for (int e = 1; e < NE; e++) mx = fmaxf(mx, logit[e]);
        float p[NE], Z = 0.f;
#pragma unroll
        for (int e = 0; e < NE; e++) { p[e] = expf(logit[e] - mx); Z += p[e]; }
#pragma unroll
        for (int e = 0; e < NE; e++) p[e] /= Z;

        // top-2 (lowest index wins ties, matching lax.top_k)
        int i0 = 0;
#pragma unroll
        for (int e = 1; e < NE; e++) if (p[e] > p[i0]) i0 = e;
        int i1 = (i0 == 0) ? 1 : 0;
#pragma unroll
        for (int e = 0; e < NE; e++) if (e != i0 && p[e] > p[i1]) i1 = e;

        float p0 = p[i0], p1 = p[i1];
        float s  = p0 + p1;
        float w0 = p0 / (s + EPSI);
        float w1 = p1 / (s + EPSI);
        float swsum = w0 + w1;
        float accw  = fmaxf(swsum, EPSI);
        float scale = 1.f + swsum * EPSI;
        float c0 = w0 / accw * scale;
        float c1 = w1 / accw * scale;

        int s0 = atomicAdd(&g_counts[i0], 1);
        g_tok[i0 * NTOK + s0]  = token;
        g_coef[i0 * NTOK + s0] = c0;
        int s1 = atomicAdd(&g_counts[i1], 1);
        g_tok[i1 * NTOK + s1]  = token;
        g_coef[i1 * NTOK + s1] = c1;
    }
}

// ---------------- bf16 split helper ----------------
__device__ __forceinline__ void split_bf16(float v, __nv_bfloat16& hi, __nv_bfloat16& lo) {
    hi = __float2bfloat16(v);
    lo = __float2bfloat16(v - __bfloat162float(hi));
}

// ---------------- grouped gather-GEMM + weighted scatter -------------------
// One block = one (expert, m_tile, n_tile). bf16x3 split for ~fp32 accuracy.
__global__ void __launch_bounds__(256, 4)
moe_gemm_kernel(const float* __restrict__ tokens,
                const float* __restrict__ ew,
                float* __restrict__ out) {
    __shared__ __align__(16) __nv_bfloat16 As_hi[BM * A_ST];
    __shared__ __align__(16) __nv_bfloat16 As_lo[BM * A_ST];
    __shared__ __align__(16) __nv_bfloat16 Bs_hi[BK * B_ST];
    __shared__ __align__(16) __nv_bfloat16 Bs_lo[BK * B_ST];
    __shared__ __align__(16) float s_out[BM * BN];
    __shared__ int   s_tok[BM];
    __shared__ float s_coef[BM];

    // map blockIdx -> (expert, m_tile, n_tile) using runtime counts
    int bid = blockIdx.x;
    int e = -1, cnt = 0;
#pragma unroll
    for (int ee = 0; ee < NE; ee++) {
        int c = g_counts[ee];
        int t = ((c + BM - 1) / BM) * NTILE;
        if (e < 0) {
            if (bid < t) { e = ee; cnt = c; }
            else bid -= t;
        }
    }
    if (e < 0) return;
    int nt = bid % NTILE;
    int mt = bid / NTILE;

    int tid = threadIdx.x;
    if (tid < BM) {
        int r = mt * BM + tid;
        bool ok = (r < cnt);
        s_tok[tid]  = ok ? g_tok[e * NTOK + r]  : -1;
        s_coef[tid] = ok ? g_coef[e * NTOK + r] : 0.f;
    }
    __syncthreads();

    wmma::fragment<wmma::accumulator, 16, 16, 16, float> accf[2];
    wmma::fill_fragment(accf[0], 0.f);
    wmma::fill_fragment(accf[1], 0.f);

    const float* Bbase = ew + (size_t)e * HDIM * HDIM + (size_t)nt * BN;

    int wid = tid >> 5;
    int wm  = wid >> 2;   // 0..1 (32 rows each)
    int wn  = wid & 3;    // 0..3 (16 cols each)

    for (int k0 = 0; k0 < HDIM; k0 += BK) {
        // --- load A tile (gathered token rows), split to hi/lo bf16 ---
        for (int f = tid; f < (BM * BK) / 4; f += 256) {
            int r  = f >> 3;            // BK/4 = 8 float4 per row
            int c4 = (f & 7) << 2;
            int tk = s_tok[r];
            float4 v = make_float4(0.f, 0.f, 0.f, 0.f);
            if (tk >= 0)
                v = *reinterpret_cast<const float4*>(&tokens[(size_t)tk * HDIM + k0 + c4]);
            __nv_bfloat16 h, l;
            int base = r * A_ST + c4;
            split_bf16(v.x, h, l); As_hi[base + 0] = h; As_lo[base + 0] = l;
            split_bf16(v.y, h, l); As_hi[base + 1] = h; As_lo[base + 1] = l;
            split_bf16(v.z, h, l); As_hi[base + 2] = h; As_lo[base + 2] = l;
            split_bf16(v.w, h, l); As_hi[base + 3] = h; As_lo[base + 3] = l;
        }
        // --- load B tile (expert weights), split to hi/lo bf16 ---
        for (int f = tid; f < (BK * BN) / 4; f += 256) {
            int r  = f >> 4;            // BN/4 = 16 float4 per row
            int c4 = (f & 15) << 2;
            float4 v = *reinterpret_cast<const float4*>(&Bbase[(size_t)(k0 + r) * HDIM + c4]);
            __nv_bfloat16 h, l;
            int base = r * B_ST + c4;
            split_bf16(v.x, h, l); Bs_hi[base + 0] = h; Bs_lo[base + 0] = l;
            split_bf16(v.y, h, l); Bs_hi[base + 1] = h; Bs_lo[base + 1] = l;
            split_bf16(v.z, h, l); Bs_hi[base + 2] = h; Bs_lo[base + 2] = l;
            split_bf16(v.w, h, l); Bs_hi[base + 3] = h; Bs_lo[base + 3] = l;
        }
        __syncthreads();

#pragma unroll
        for (int kk = 0; kk < BK; kk += 16) {
            wmma::fragment<wmma::matrix_b, 16, 16, 16, __nv_bfloat16, wmma::row_major> bh, bl;
            wmma::load_matrix_sync(bh, &Bs_hi[kk * B_ST + wn * 16], B_ST);
            wmma::load_matrix_sync(bl, &Bs_lo[kk * B_ST + wn * 16], B_ST);
#pragma unroll
            for (int i = 0; i < 2; i++) {
                int row = wm * 32 + i * 16;
                wmma::fragment<wmma::matrix_a, 16, 16, 16, __nv_bfloat16, wmma::row_major> ah, al;
                wmma::load_matrix_sync(ah, &As_hi[row * A_ST + kk], A_ST);
                wmma::load_matrix_sync(al, &As_lo[row * A_ST + kk], A_ST);
                wmma::mma_sync(accf[i], ah, bh, accf[i]);  // hi*hi
                wmma::mma_sync(accf[i], al, bh, accf[i]);  // lo*hi
                wmma::mma_sync(accf[i], ah, bl, accf[i]);  // hi*lo
            }
        }
        __syncthreads();
    }

    // --- epilogue: stage to smem, weighted atomic scatter to out ---
#pragma unroll
    for (int i = 0; i < 2; i++) {
        int row = wm * 32 + i * 16;
        wmma::store_matrix_sync(&s_out[row * BN + wn * 16], accf[i], BN, wmma::mem_row_major);
    }
    __syncthreads();

    for (int f = tid; f < BM * BN; f += 256) {
        int r = f >> 6;       // BN = 64
        int c = f & 63;
        int tk = s_tok[r];
        if (tk >= 0)
            atomicAdd(&out[(size_t)tk * HDIM + (size_t)nt * BN + c], s_coef[r] * s_out[f]);
    }
}

// ---------------- launch ----------------
extern "C" void kernel_launch(void* const* d_in, const int* in_sizes, int n_in,
                              void* d_out, int out_size) {
    const float* tokens = (const float*)d_in[0];   // [4,2048,1024]
    const float* rw     = (const float*)d_in[1];   // [8,1024]
    const float* rb     = (const float*)d_in[2];   // [8]
    const float* ew     = (const float*)d_in[3];   // [8,1024,1024]
    float* out = (float*)d_out;                    // [4,2048,1024]

    cudaMemsetAsync(d_out, 0, (size_t)out_size * sizeof(float), 0);
    zero_counts_kernel<<<1, 32>>>();
    router_kernel<<<NTOK / 8, 256>>>(tokens, rw, rb);
    moe_gemm_kernel<<<MAX_TILES, 256>>>(tokens, ew, out);
    (void)in_sizes; (void)n_in;
}

// round 3
// speedup vs baseline: 1.9014x; 1.9014x over previous
#include <cuda_runtime.h>
#include <cuda_bf16.h>
#include <cstdint>

// Problem constants (B=4, S=2048, H=1024, E=8, TOP_K=2)
#define NE    8
#define NTOK  8192
#define HDIM  1024
#define EPSI  1e-10f

// GEMM tiling
#define BM 128
#define BN 128
#define BK 32
#define NTILES (HDIM / BN)          // 8
#define MAXMT  (NTOK * 2 / BM + NE) // 136
#define MAXROWS (MAXMT * BM)        // 17408

// SMEM: 2 stages; per stage A_hi/A_lo/B_hi/B_lo each 128 rows x 40 bf16 (80B stride)
#define ROWST 40                    // elements; 80 bytes, conflict-free for ldmatrix
#define TILE_B (128 * ROWST * 2)    // 10240 bytes per sub-tile
#define ST_BYTES (4 * TILE_B)       // 40960
#define SM_AHI 0
#define SM_ALO (1 * TILE_B)
#define SM_BHI (2 * TILE_B)
#define SM_BLO (3 * TILE_B)
#define SMEM_TOTAL (2 * ST_BYTES)   // 81920

// ---------------- device scratch (static, allocation-free) ----------------
__device__ int   g_counts[NE];
__device__ int   g_tok[NE * NTOK];
__device__ int   g_off[NE];
__device__ int   g_mtile_e[MAXMT];
__device__ int   g_num_mtiles;
__device__ int   g_total_rows;
__device__ int   g_texp[NTOK * 2];
__device__ int   g_tslot[NTOK * 2];
__device__ float g_tcoef[NTOK * 2];

__device__ __align__(16) __nv_bfloat16 X_hi[(size_t)MAXROWS * HDIM];
__device__ __align__(16) __nv_bfloat16 X_lo[(size_t)MAXROWS * HDIM];
__device__ __align__(16) __nv_bfloat16 WT_hi[(size_t)NE * HDIM * HDIM];
__device__ __align__(16) __nv_bfloat16 WT_lo[(size_t)NE * HDIM * HDIM];
__device__ __align__(16) float Y[(size_t)MAXROWS * HDIM];

// ---------------- PTX helpers ----------------
__device__ __forceinline__ uint32_t smem_u32(const void* p) {
    uint32_t a;
    asm("{ .reg .u64 t; cvta.to.shared.u64 t, %1; cvt.u32.u64 %0, t; }" : "=r"(a) : "l"(p));
    return a;
}
__device__ __forceinline__ void cp16(uint32_t dst, const void* src) {
    asm volatile("cp.async.cg.shared.global [%0], [%1], 16;" :: "r"(dst), "l"(src));
}
#define CP_COMMIT() asm volatile("cp.async.commit_group;" ::: "memory")
#define CP_WAIT(n)  asm volatile("cp.async.wait_group %0;" :: "n"(n) : "memory")

__device__ __forceinline__ void ldm_x4(uint32_t* r, uint32_t addr) {
    asm volatile("ldmatrix.sync.aligned.m8n8.x4.shared.b16 {%0,%1,%2,%3}, [%4];"
                 : "=r"(r[0]), "=r"(r[1]), "=r"(r[2]), "=r"(r[3]) : "r"(addr));
}
__device__ __forceinline__ void mma_bf16(float* d, const uint32_t* a, const uint32_t* b) {
    asm volatile("mma.sync.aligned.m16n8k16.row.col.f32.bf16.bf16.f32 "
                 "{%0,%1,%2,%3}, {%4,%5,%6,%7}, {%8,%9}, {%0,%1,%2,%3};"
                 : "+f"(d[0]), "+f"(d[1]), "+f"(d[2]), "+f"(d[3])
                 : "r"(a[0]), "r"(a[1]), "r"(a[2]), "r"(a[3]), "r"(b[0]), "r"(b[1]));
}
__device__ __forceinline__ void split_bf16(float v, __nv_bfloat16& h, __nv_bfloat16& l) {
    h = __float2bfloat16(v);
    l = __float2bfloat16(v - __bfloat162float(h));
}

// ---------------- kernels ----------------
__global__ void zero_counts_kernel() {
    if (threadIdx.x < NE) g_counts[threadIdx.x] = 0;
}

__global__ void router_kernel(const float* __restrict__ tokens,
                              const float* __restrict__ rw,
                              const float* __restrict__ rb) {
    __shared__ float sw[NE * HDIM];
    int tid = threadIdx.x;
    for (int i = tid; i < NE * HDIM; i += blockDim.x) sw[i] = rw[i];
    __syncthreads();

    int warp = tid >> 5, lane = tid & 31;
    int token = blockIdx.x * 8 + warp;
    if (token >= NTOK) return;

    const float* x = tokens + (size_t)token * HDIM;
    float acc[NE];
#pragma unroll
    for (int e = 0; e < NE; e++) acc[e] = 0.f;
    for (int i = lane; i < HDIM; i += 32) {
        float xv = x[i];
#pragma unroll
        for (int e = 0; e < NE; e++) acc[e] += xv * sw[e * HDIM + i];
    }
#pragma unroll
    for (int off = 16; off > 0; off >>= 1)
#pragma unroll
        for (int e = 0; e < NE; e++) acc[e] += __shfl_xor_sync(0xffffffffu, acc[e], off);

    if (lane == 0) {
        float lg[NE];
#pragma unroll
        for (int e = 0; e < NE; e++) lg[e] = acc[e] + rb[e];
        float mx = lg[0];
#pragma unroll
        for (int e = 1; e < NE; e++) mx = fmaxf(mx, lg[e]);
        float p[NE], Z = 0.f;
#pragma unroll
        for (int e = 0; e < NE; e++) { p[e] = expf(lg[e] - mx); Z += p[e]; }
#pragma unroll
        for (int e = 0; e < NE; e++) p[e] /= Z;

        int i0 = 0;
#pragma unroll
        for (int e = 1; e < NE; e++) if (p[e] > p[i0]) i0 = e;
        int i1 = (i0 == 0) ? 1 : 0;
#pragma unroll
        for (int e = 0; e < NE; e++) if (e != i0 && p[e] > p[i1]) i1 = e;

        float p0 = p[i0], p1 = p[i1];
        float s = p0 + p1;
        float w0 = p0 / (s + EPSI), w1 = p1 / (s + EPSI);
        float swsum = w0 + w1;
        float accw = fmaxf(swsum, EPSI);
        float scale = 1.f + swsum * EPSI;
        float c0 = w0 / accw * scale, c1 = w1 / accw * scale;

        int s0 = atomicAdd(&g_counts[i0], 1);
        g_tok[i0 * NTOK + s0] = token;
        g_texp[token * 2 + 0] = i0; g_tslot[token * 2 + 0] = s0; g_tcoef[token * 2 + 0] = c0;
        int s1 = atomicAdd(&g_counts[i1], 1);
        g_tok[i1 * NTOK + s1] = token;
        g_texp[token * 2 + 1] = i1; g_tslot[token * 2 + 1] = s1; g_tcoef[token * 2 + 1] = c1;
    }
}

__global__ void offsets_kernel() {
    if (threadIdx.x != 0) return;
    int off = 0, mti = 0;
    for (int e = 0; e < NE; e++) {
        g_off[e] = off;
        int cp = ((g_counts[e] + BM - 1) / BM) * BM;
        for (int t = 0; t < cp / BM; t++) g_mtile_e[mti++] = e;
        off += cp;
    }
    g_total_rows = off;
    g_num_mtiles = mti;
}

// gather + fp32->bf16 hi/lo split of token rows into dense per-expert X
__global__ void gather_kernel(const float* __restrict__ tokens) {
    int row = blockIdx.x;
    if (row >= g_total_rows) return;
    int e = 0;
#pragma unroll
    for (int i = 1; i < NE; i++) if (row >= g_off[i]) e = i;
    int slot = row - g_off[e];
    int tid = threadIdx.x;                 // 128 threads, 8 elems each
    size_t dst = (size_t)row * HDIM + tid * 8;

    __align__(16) __nv_bfloat16 h[8], l[8];
    if (slot < g_counts[e]) {
        int tok = g_tok[e * NTOK + slot];
        const float4* s = reinterpret_cast<const float4*>(&tokens[(size_t)tok * HDIM + tid * 8]);
        float4 a = s[0], b = s[1];
        split_bf16(a.x, h[0], l[0]); split_bf16(a.y, h[1], l[1]);
        split_bf16(a.z, h[2], l[2]); split_bf16(a.w, h[3], l[3]);
        split_bf16(b.x, h[4], l[4]); split_bf16(b.y, h[5], l[5]);
        split_bf16(b.z, h[6], l[6]); split_bf16(b.w, h[7], l[7]);
    } else {
#pragma unroll
        for (int i = 0; i < 8; i++) { h[i] = __float2bfloat16(0.f); l[i] = h[i]; }
    }
    *reinterpret_cast<uint4*>(&X_hi[dst]) = *reinterpret_cast<const uint4*>(h);
    *reinterpret_cast<uint4*>(&X_lo[dst]) = *reinterpret_cast<const uint4*>(l);
}

// transpose expert weights [E][K][N] -> [E][N][K] bf16 hi/lo
__global__ void wtrans_kernel(const float* __restrict__ ew) {
    __shared__ float t[32][33];
    int e = blockIdx.z, kt = blockIdx.x, nt = blockIdx.y;
    int tx = threadIdx.x, ty = threadIdx.y;   // 32 x 8
    const float* src = ew + ((size_t)e * HDIM + kt * 32) * HDIM + nt * 32;
#pragma unroll
    for (int i = 0; i < 4; i++)
        t[ty + i * 8][tx] = src[(size_t)(ty + i * 8) * HDIM + tx];
    __syncthreads();
    size_t dbase = ((size_t)e * HDIM + nt * 32) * HDIM + kt * 32;
#pragma unroll
    for (int i = 0; i < 4; i++) {
        float v = t[tx][ty + i * 8];
        __nv_bfloat16 h, l; split_bf16(v, h, l);
        WT_hi[dbase + (size_t)(ty + i * 8) * HDIM + tx] = h;
        WT_lo[dbase + (size_t)(ty + i * 8) * HDIM + tx] = l;
    }
}

// ---------------- HMMA grouped GEMM: Y[rows, :] = X @ W_e^T --------------
// 128x128 tile, 8 warps (2x4), warp tile 64x32, bf16x3 split, cp.async x2.
__global__ void __launch_bounds__(256, 2) moe_gemm_mma() {
    extern __shared__ __align__(16) char smem[];
    int mt = blockIdx.x >> 3;      // NTILES = 8
    int nt = blockIdx.x & 7;
    if (mt >= g_num_mtiles) return;
    int e = g_mtile_e[mt];
    int row_base = mt * BM;
    int col_base = nt * BN;

    uint32_t sb = smem_u32(smem);
    int tid = threadIdx.x, wid = tid >> 5, lane = tid & 31;
    int wm = wid >> 2, wn = wid & 3;              // warp tile: rows wm*64, cols wn*32
    int g = lane >> 2, tg = lane & 3;             // mma group / thread-in-group

    const size_t wbase = ((size_t)e * HDIM + col_base) * HDIM;

    auto load_stage = [&](int c, int s) {
        uint32_t st = sb + s * ST_BYTES;
        int k0 = c * BK;
        // each sub-tile: 128 rows x 32 bf16 (64B = 4 x 16B chunks); 512 cp16 / 256 thr
#pragma unroll
        for (int j = 0; j < 2; j++) {
            int u = tid + j * 256;
            int r = u >> 2, cc = (u & 3) << 4;    // byte offset within row
            uint32_t off = (uint32_t)(r * (ROWST * 2)) + cc;
            size_t soA = (size_t)(row_base + r) * HDIM + k0 + (cc >> 1);
            size_t soB = wbase + (size_t)r * HDIM + k0 + (cc >> 1);
            cp16(st + SM_AHI + off, &X_hi[soA]);
            cp16(st + SM_ALO + off, &X_lo[soA]);
            cp16(st + SM_BHI + off, &WT_hi[soB]);
            cp16(st + SM_BLO + off, &WT_lo[soB]);
        }
        CP_COMMIT();
    };

    float acc[4][4][4];
#pragma unroll
    for (int i = 0; i < 4; i++)
#pragma unroll
        for (int j = 0; j < 4; j++)
#pragma unroll
            for (int q = 0; q < 4; q++) acc[i][j][q] = 0.f;

    load_stage(0, 0);
    load_stage(1, 1);

    // ldmatrix lane address offsets (element units within a [128][ROWST] tile)
    int a_row = wm * 64 + (lane & 15);            // + mi*16
    int a_colsel = (lane >> 4) * 8;               // 0 or 8
    int b_row = wn * 32 + (lane & 7) + ((lane >> 4) << 3);   // + ni*16
    int b_colsel = ((lane >> 3) & 1) * 8;

    const int NIT = HDIM / BK;                    // 32
    for (int c = 0; c < NIT; c++) {
        int s = c & 1;
        CP_WAIT(1);
        __syncthreads();
        uint32_t st = sb + s * ST_BYTES;

#pragma unroll
        for (int kk = 0; kk < BK; kk += 16) {
            uint32_t bh[2][4], bl[2][4];
#pragma unroll
            for (int nb = 0; nb < 2; nb++) {      // each x4 covers two n8 tiles
                uint32_t boff = (uint32_t)((b_row + nb * 16) * (ROWST * 2) + (kk + b_colsel) * 2);
                ldm_x4(bh[nb], st + SM_BHI + boff);
                ldm_x4(bl[nb], st + SM_BLO + boff);
            }
#pragma unroll
            for (int mi = 0; mi < 4; mi++) {
                uint32_t ah[4], al[4];
                uint32_t aoff = (uint32_t)((a_row + mi * 16) * (ROWST * 2) + (kk + a_colsel) * 2);
                ldm_x4(ah, st + SM_AHI + aoff);
                ldm_x4(al, st + SM_ALO + aoff);
#pragma unroll
                for (int ni = 0; ni < 4; ni++)
                    mma_bf16(acc[mi][ni], ah, &bh[ni >> 1][(ni & 1) * 2]);
#pragma unroll
                for (int ni = 0; ni < 4; ni++)
                    mma_bf16(acc[mi][ni], al, &bh[ni >> 1][(ni & 1) * 2]);
#pragma unroll
                for (int ni = 0; ni < 4; ni++)
                    mma_bf16(acc[mi][ni], ah, &bl[ni >> 1][(ni & 1) * 2]);
            }
        }
        __syncthreads();
        if (c + 2 < NIT) load_stage(c + 2, s);
    }

    // ---- epilogue: stage accumulators in SMEM (reuse stages), coalesced out
    float* s_out = reinterpret_cast<float*>(smem);   // [128][132]
#pragma unroll
    for (int mi = 0; mi < 4; mi++)
#pragma unroll
        for (int ni = 0; ni < 4; ni++) {
            int r0 = wm * 64 + mi * 16 + g;
            int cc = wn * 32 + ni * 8 + tg * 2;
            *reinterpret_cast<float2*>(&s_out[r0 * 132 + cc]) =
                make_float2(acc[mi][ni][0], acc[mi][ni][1]);
            *reinterpret_cast<float2*>(&s_out[(r0 + 8) * 132 + cc]) =
                make_float2(acc[mi][ni][2], acc[mi][ni][3]);
        }
    __syncthreads();

#pragma unroll
    for (int i = 0; i < 16; i++) {
        int u = tid + i * 256;                    // 4096 float4 slots
        int r = u >> 5, cc = (u & 31) << 2;
        float4 v = *reinterpret_cast<const float4*>(&s_out[r * 132 + cc]);
        *reinterpret_cast<float4*>(&Y[(size_t)(row_base + r) * HDIM + col_base + cc]) = v;
    }
}

// combine: out[t] = c0 * Y[row0] + c1 * Y[row1]
__global__ void combine_kernel(float* __restrict__ out) {
    int t = blockIdx.x;
    int e0 = g_texp[2 * t], e1 = g_texp[2 * t + 1];
    size_t r0 = (size_t)(g_off[e0] + g_tslot[2 * t]);
    size_t r1 = (size_t)(g_off[e1] + g_tslot[2 * t + 1]);
    float c0 = g_tcoef[2 * t], c1 = g_tcoef[2 * t + 1];
    int i = threadIdx.x * 4;
    float4 y0 = *reinterpret_cast<const float4*>(&Y[r0 * HDIM + i]);
    float4 y1 = *reinterpret_cast<const float4*>(&Y[r1 * HDIM + i]);
    float4 o;
    o.x = c0 * y0.x + c1 * y1.x;
    o.y = c0 * y0.y + c1 * y1.y;
    o.z = c0 * y0.z + c1 * y1.z;
    o.w = c0 * y0.w + c1 * y1.w;
    *reinterpret_cast<float4*>(&out[(size_t)t * HDIM + i]) = o;
}

// ---------------- launch ----------------
extern "C" void kernel_launch(void* const* d_in, const int* in_sizes, int n_in,
                              void* d_out, int out_size) {
    const float* tokens = (const float*)d_in[0];   // [4,2048,1024]
    const float* rw     = (const float*)d_in[1];   // [8,1024]
    const float* rb     = (const float*)d_in[2];   // [8]
    const float* ew     = (const float*)d_in[3];   // [8,1024,1024]
    float* out = (float*)d_out;

    cudaFuncSetAttribute(moe_gemm_mma, cudaFuncAttributeMaxDynamicSharedMemorySize, SMEM_TOTAL);

    zero_counts_kernel<<<1, 32>>>();
    wtrans_kernel<<<dim3(32, 32, 8), dim3(32, 8)>>>(ew);
    router_kernel<<<NTOK / 8, 256>>>(tokens, rw, rb);
    offsets_kernel<<<1, 32>>>();
    gather_kernel<<<MAXROWS, 128>>>(tokens);
    moe_gemm_mma<<<MAXMT * NTILES, 256, SMEM_TOTAL>>>();
    combine_kernel<<<NTOK, 256>>>(out);
    (void)in_sizes; (void)n_in; (void)out_size;
}

// round 4
// speedup vs baseline: 2.4635x; 1.2956x over previous
#include <cuda_runtime.h>
#include <cuda_fp16.h>
#include <cstdint>

// Problem constants (B=4, S=2048, H=1024, E=8, TOP_K=2)
#define NE    8
#define NTOK  8192
#define HDIM  1024
#define EPSI  1e-10f

// GEMM tiling
#define BM 128
#define BN 128
#define BK 32
#define NTILES (HDIM / BN)          // 8
#define MAXMT  (NTOK * 2 / BM + NE) // 136
#define MAXROWS (MAXMT * BM)        // 17408

// SMEM: 3 stages; per stage A_hi/A_lo/B each 128 rows x 40 fp16 (80B stride)
#define ROWST 40                    // elements; 80B stride, conflict-free ldmatrix
#define TILE_B (128 * ROWST * 2)    // 10240 bytes per sub-tile
#define ST_BYTES (3 * TILE_B)       // 30720
#define SM_AHI 0
#define SM_ALO (1 * TILE_B)
#define SM_B   (2 * TILE_B)
#define NSTAGE 3
#define SMEM_TOTAL (NSTAGE * ST_BYTES)   // 92160 (epilogue 67584B reused inside)

// ---------------- device scratch (static, allocation-free) ----------------
__device__ int   g_counts[NE];
__device__ int   g_tok[NE * NTOK];
__device__ int   g_off[NE];
__device__ int   g_mtile_e[MAXMT];
__device__ int   g_num_mtiles;
__device__ int   g_total_rows;
__device__ int   g_texp[NTOK * 2];
__device__ int   g_tslot[NTOK * 2];
__device__ float g_tcoef[NTOK * 2];

__device__ __align__(16) __half X_hi[(size_t)MAXROWS * HDIM];
__device__ __align__(16) __half X_lo[(size_t)MAXROWS * HDIM];
__device__ __align__(16) __half WT_h[(size_t)NE * HDIM * HDIM];
__device__ __align__(16) float  Y[(size_t)MAXROWS * HDIM];

// ---------------- PTX helpers ----------------
__device__ __forceinline__ uint32_t smem_u32(const void* p) {
    uint32_t a;
    asm("{ .reg .u64 t; cvta.to.shared.u64 t, %1; cvt.u32.u64 %0, t; }" : "=r"(a) : "l"(p));
    return a;
}
__device__ __forceinline__ void cp16(uint32_t dst, const void* src) {
    asm volatile("cp.async.cg.shared.global [%0], [%1], 16;" :: "r"(dst), "l"(src));
}
#define CP_COMMIT() asm volatile("cp.async.commit_group;" ::: "memory")
#define CP_WAIT(n)  asm volatile("cp.async.wait_group %0;" :: "n"(n) : "memory")

__device__ __forceinline__ void ldm_x4(uint32_t* r, uint32_t addr) {
    asm volatile("ldmatrix.sync.aligned.m8n8.x4.shared.b16 {%0,%1,%2,%3}, [%4];"
                 : "=r"(r[0]), "=r"(r[1]), "=r"(r[2]), "=r"(r[3]) : "r"(addr));
}
__device__ __forceinline__ void mma_fp16(float* d, const uint32_t* a, const uint32_t* b) {
    asm volatile("mma.sync.aligned.m16n8k16.row.col.f32.f16.f16.f32 "
                 "{%0,%1,%2,%3}, {%4,%5,%6,%7}, {%8,%9}, {%0,%1,%2,%3};"
                 : "+f"(d[0]), "+f"(d[1]), "+f"(d[2]), "+f"(d[3])
                 : "r"(a[0]), "r"(a[1]), "r"(a[2]), "r"(a[3]), "r"(b[0]), "r"(b[1]));
}
__device__ __forceinline__ void split_fp16(float v, __half& h, __half& l) {
    h = __float2half_rn(v);
    l = __float2half_rn(v - __half2float(h));
}

// ---------------- kernels ----------------
__global__ void zero_counts_kernel() {
    if (threadIdx.x < NE) g_counts[threadIdx.x] = 0;
}

__global__ void router_kernel(const float* __restrict__ tokens,
                              const float* __restrict__ rw,
                              const float* __restrict__ rb) {
    __shared__ float sw[NE * HDIM];
    int tid = threadIdx.x;
    for (int i = tid; i < NE * HDIM; i += blockDim.x) sw[i] = rw[i];
    __syncthreads();

    int warp = tid >> 5, lane = tid & 31;
    int token = blockIdx.x * 8 + warp;
    if (token >= NTOK) return;

    const float* x = tokens + (size_t)token * HDIM;
    float acc[NE];
#pragma unroll
    for (int e = 0; e < NE; e++) acc[e] = 0.f;
    for (int i = lane; i < HDIM; i += 32) {
        float xv = x[i];
#pragma unroll
        for (int e = 0; e < NE; e++) acc[e] += xv * sw[e * HDIM + i];
    }
#pragma unroll
    for (int off = 16; off > 0; off >>= 1)
#pragma unroll
        for (int e = 0; e < NE; e++) acc[e] += __shfl_xor_sync(0xffffffffu, acc[e], off);

    if (lane == 0) {
        float lg[NE];
#pragma unroll
        for (int e = 0; e < NE; e++) lg[e] = acc[e] + rb[e];
        float mx = lg[0];
#pragma unroll
        for (int e = 1; e < NE; e++) mx = fmaxf(mx, lg[e]);
        float p[NE], Z = 0.f;
#pragma unroll
        for (int e = 0; e < NE; e++) { p[e] = expf(lg[e] - mx); Z += p[e]; }
#pragma unroll
        for (int e = 0; e < NE; e++) p[e] /= Z;

        int i0 = 0;
#pragma unroll
        for (int e = 1; e < NE; e++) if (p[e] > p[i0]) i0 = e;
        int i1 = (i0 == 0) ? 1 : 0;
#pragma unroll
        for (int e = 0; e < NE; e++) if (e != i0 && p[e] > p[i1]) i1 = e;

        float p0 = p[i0], p1 = p[i1];
        float s = p0 + p1;
        float w0 = p0 / (s + EPSI), w1 = p1 / (s + EPSI);
        float swsum = w0 + w1;
        float accw = fmaxf(swsum, EPSI);
        float scale = 1.f + swsum * EPSI;
        float c0 = w0 / accw * scale, c1 = w1 / accw * scale;

        int s0 = atomicAdd(&g_counts[i0], 1);
        g_tok[i0 * NTOK + s0] = token;
        g_texp[token * 2 + 0] = i0; g_tslot[token * 2 + 0] = s0; g_tcoef[token * 2 + 0] = c0;
        int s1 = atomicAdd(&g_counts[i1], 1);
        g_tok[i1 * NTOK + s1] = token;
        g_texp[token * 2 + 1] = i1; g_tslot[token * 2 + 1] = s1; g_tcoef[token * 2 + 1] = c1;
    }
}

__global__ void offsets_kernel() {
    if (threadIdx.x != 0) return;
    int off = 0, mti = 0;
    for (int e = 0; e < NE; e++) {
        g_off[e] = off;
        int cp = ((g_counts[e] + BM - 1) / BM) * BM;
        for (int t = 0; t < cp / BM; t++) g_mtile_e[mti++] = e;
        off += cp;
    }
    g_total_rows = off;
    g_num_mtiles = mti;
}

// gather + fp32->fp16 hi/lo split of token rows into dense per-expert X
__global__ void gather_kernel(const float* __restrict__ tokens) {
    int row = blockIdx.x;
    if (row >= g_total_rows) return;
    int e = 0;
#pragma unroll
    for (int i = 1; i < NE; i++) if (row >= g_off[i]) e = i;
    int slot = row - g_off[e];
    int tid = threadIdx.x;                 // 128 threads, 8 elems each
    size_t dst = (size_t)row * HDIM + tid * 8;

    __align__(16) __half h[8], l[8];
    if (slot < g_counts[e]) {
        int tok = g_tok[e * NTOK + slot];
        const float4* s = reinterpret_cast<const float4*>(&tokens[(size_t)tok * HDIM + tid * 8]);
        float4 a = s[0], b = s[1];
        split_fp16(a.x, h[0], l[0]); split_fp16(a.y, h[1], l[1]);
        split_fp16(a.z, h[2], l[2]); split_fp16(a.w, h[3], l[3]);
        split_fp16(b.x, h[4], l[4]); split_fp16(b.y, h[5], l[5]);
        split_fp16(b.z, h[6], l[6]); split_fp16(b.w, h[7], l[7]);
    } else {
#pragma unroll
        for (int i = 0; i < 8; i++) { h[i] = __float2half_rn(0.f); l[i] = h[i]; }
    }
    *reinterpret_cast<uint4*>(&X_hi[dst]) = *reinterpret_cast<const uint4*>(h);
    *reinterpret_cast<uint4*>(&X_lo[dst]) = *reinterpret_cast<const uint4*>(l);
}

// transpose expert weights [E][K][N] -> [E][N][K] fp16 (single)
__global__ void wtrans_kernel(const float* __restrict__ ew) {
    __shared__ float t[32][33];
    int e = blockIdx.z, kt = blockIdx.x, nt = blockIdx.y;
    int tx = threadIdx.x, ty = threadIdx.y;   // 32 x 8
    const float* src = ew + ((size_t)e * HDIM + kt * 32) * HDIM + nt * 32;
#pragma unroll
    for (int i = 0; i < 4; i++)
        t[ty + i * 8][tx] = src[(size_t)(ty + i * 8) * HDIM + tx];
    __syncthreads();
    size_t dbase = ((size_t)e * HDIM + nt * 32) * HDIM + kt * 32;
#pragma unroll
    for (int i = 0; i < 4; i++)
        WT_h[dbase + (size_t)(ty + i * 8) * HDIM + tx] = __float2half_rn(t[tx][ty + i * 8]);
}

// ---------------- HMMA grouped GEMM: Y[rows, :] = X @ W_e^T --------------
// 128x128 tile, 8 warps (2x4), warp tile 64x32, fp16x2 split (A hi/lo, B hi),
// 3-stage cp.async pipeline.
__global__ void __launch_bounds__(256, 2) moe_gemm_mma() {
    extern __shared__ __align__(16) char smem[];
    int mt = blockIdx.x >> 3;      // NTILES = 8
    int nt = blockIdx.x & 7;
    if (mt >= g_num_mtiles) return;
    int e = g_mtile_e[mt];
    int row_base = mt * BM;
    int col_base = nt * BN;

    uint32_t sb = smem_u32(smem);
    int tid = threadIdx.x, wid = tid >> 5, lane = tid & 31;
    int wm = wid >> 2, wn = wid & 3;              // warp tile: rows wm*64, cols wn*32
    int g = lane >> 2, tg = lane & 3;

    const size_t wbase = ((size_t)e * HDIM + col_base) * HDIM;

    auto load_stage = [&](int c, int s) {
        uint32_t st = sb + s * ST_BYTES;
        int k0 = c * BK;
        // each sub-tile: 128 rows x 32 fp16 (64B = 4 x 16B chunks)
#pragma unroll
        for (int j = 0; j < 2; j++) {
            int u = tid + j * 256;
            int r = u >> 2, cc = (u & 3) << 4;    // byte offset within row
            uint32_t off = (uint32_t)(r * (ROWST * 2)) + cc;
            size_t soA = (size_t)(row_base + r) * HDIM + k0 + (cc >> 1);
            size_t soB = wbase + (size_t)r * HDIM + k0 + (cc >> 1);
            cp16(st + SM_AHI + off, &X_hi[soA]);
            cp16(st + SM_ALO + off, &X_lo[soA]);
            cp16(st + SM_B   + off, &WT_h[soB]);
        }
        CP_COMMIT();
    };

    float acc[4][4][4];
#pragma unroll
    for (int i = 0; i < 4; i++)
#pragma unroll
        for (int j = 0; j < 4; j++)
#pragma unroll
            for (int q = 0; q < 4; q++) acc[i][j][q] = 0.f;

    load_stage(0, 0);
    load_stage(1, 1);
    load_stage(2, 2);

    // ldmatrix lane address components (element units in a [128][ROWST] tile)
    int a_row = wm * 64 + (lane & 15);            // + mi*16
    int a_colsel = (lane >> 4) * 8;               // 0 or 8
    int b_row = wn * 32 + (lane & 7) + ((lane >> 4) << 3);   // + nb*16
    int b_colsel = ((lane >> 3) & 1) * 8;

    const int NIT = HDIM / BK;                    // 32
    int s = 0;
    for (int c = 0; c < NIT; c++) {
        CP_WAIT(2);
        __syncthreads();
        uint32_t st = sb + s * ST_BYTES;

#pragma unroll
        for (int kk = 0; kk < BK; kk += 16) {
            uint32_t bh[2][4];
#pragma unroll
            for (int nb = 0; nb < 2; nb++) {      // each x4 covers two n8 tiles
                uint32_t boff = (uint32_t)((b_row + nb * 16) * (ROWST * 2) + (kk + b_colsel) * 2);
                ldm_x4(bh[nb], st + SM_B + boff);
            }
#pragma unroll
            for (int mi = 0; mi < 4; mi++) {
                uint32_t ah[4], al[4];
                uint32_t aoff = (uint32_t)((a_row + mi * 16) * (ROWST * 2) + (kk + a_colsel) * 2);
                ldm_x4(ah, st + SM_AHI + aoff);
                ldm_x4(al, st + SM_ALO + aoff);
#pragma unroll
                for (int ni = 0; ni < 4; ni++)
                    mma_fp16(acc[mi][ni], ah, &bh[ni >> 1][(ni & 1) * 2]);
#pragma unroll
                for (int ni = 0; ni < 4; ni++)
                    mma_fp16(acc[mi][ni], al, &bh[ni >> 1][(ni & 1) * 2]);
            }
        }
        __syncthreads();
        if (c + NSTAGE < NIT) load_stage(c + NSTAGE, s);
        else CP_COMMIT();                         // empty group keeps pending-count invariant
        s = (s == NSTAGE - 1) ? 0 : s + 1;
    }

    // ---- epilogue: stage accumulators in SMEM (reuse stages), coalesced out
    float* s_out = reinterpret_cast<float*>(smem);   // [128][132] = 67584B < 92160B
#pragma unroll
    for (int mi = 0; mi < 4; mi++)
#pragma unroll
        for (int ni = 0; ni < 4; ni++) {
            int r0 = wm * 64 + mi * 16 + g;
            int cc = wn * 32 + ni * 8 + tg * 2;
            *reinterpret_cast<float2*>(&s_out[r0 * 132 + cc]) =
                make_float2(acc[mi][ni][0], acc[mi][ni][1]);
            *reinterpret_cast<float2*>(&s_out[(r0 + 8) * 132 + cc]) =
                make_float2(acc[mi][ni][2], acc[mi][ni][3]);
        }
    __syncthreads();

#pragma unroll
    for (int i = 0; i < 16; i++) {
        int u = tid + i * 256;                    // 4096 float4 slots
        int r = u >> 5, cc = (u & 31) << 2;
        float4 v = *reinterpret_cast<const float4*>(&s_out[r * 132 + cc]);
        *reinterpret_cast<float4*>(&Y[(size_t)(row_base + r) * HDIM + col_base + cc]) = v;
    }
}

// combine: out[t] = c0 * Y[row0] + c1 * Y[row1]
__global__ void combine_kernel(float* __restrict__ out) {
    int t = blockIdx.x;
    int e0 = g_texp[2 * t], e1 = g_texp[2 * t + 1];
    size_t r0 = (size_t)(g_off[e0] + g_tslot[2 * t]);
    size_t r1 = (size_t)(g_off[e1] + g_tslot[2 * t + 1]);
    float c0 = g_tcoef[2 * t], c1 = g_tcoef[2 * t + 1];
    int i = threadIdx.x * 4;
    float4 y0 = *reinterpret_cast<const float4*>(&Y[r0 * HDIM + i]);
    float4 y1 = *reinterpret_cast<const float4*>(&Y[r1 * HDIM + i]);
    float4 o;
    o.x = c0 * y0.x + c1 * y1.x;
    o.y = c0 * y0.y + c1 * y1.y;
    o.z = c0 * y0.z + c1 * y1.z;
    o.w = c0 * y0.w + c1 * y1.w;
    *reinterpret_cast<float4*>(&out[(size_t)t * HDIM + i]) = o;
}

// ---------------- launch ----------------
extern "C" void kernel_launch(void* const* d_in, const int* in_sizes, int n_in,
                              void* d_out, int out_size) {
    const float* tokens = (const float*)d_in[0];   // [4,2048,1024]
    const float* rw     = (const float*)d_in[1];   // [8,1024]
    const float* rb     = (const float*)d_in[2];   // [8]
    const float* ew     = (const float*)d_in[3];   // [8,1024,1024]
    float* out = (float*)d_out;

    cudaFuncSetAttribute(moe_gemm_mma, cudaFuncAttributeMaxDynamicSharedMemorySize, SMEM_TOTAL);

    zero_counts_kernel<<<1, 32>>>();
    wtrans_kernel<<<dim3(32, 32, 8), dim3(32, 8)>>>(ew);
    router_kernel<<<NTOK / 8, 256>>>(tokens, rw, rb);
    offsets_kernel<<<1, 32>>>();
    gather_kernel<<<MAXROWS, 128>>>(tokens);
    moe_gemm_mma<<<MAXMT * NTILES, 256, SMEM_TOTAL>>>();
    combine_kernel<<<NTOK, 256>>>(out);
    (void)in_sizes; (void)n_in; (void)out_size;
}

// round 5
// speedup vs baseline: 3.3907x; 1.3764x over previous
#include <cuda_runtime.h>
#include <cuda_fp16.h>
#include <cstdint>

// Problem constants (B=4, S=2048, H=1024, E=8, TOP_K=2)
#define NE    8
#define NTOK  8192
#define HDIM  1024
#define EPSI  1e-10f

// GEMM tiling
#define BM 128
#define BN 128
#define BK 32
#define NTILES (HDIM / BN)          // 8
#define MAXMT  (NTOK * 2 / BM + NE) // 136
#define MAXROWS (MAXMT * BM)        // 17408

// SMEM: 4 stages; per stage A/B each 128 rows x 40 fp16 (80B stride)
#define ROWST 40                    // elements; 80B stride, conflict-free ldmatrix
#define TILE_B (128 * ROWST * 2)    // 10240 bytes per sub-tile
#define ST_BYTES (2 * TILE_B)       // 20480
#define SM_A 0
#define SM_B TILE_B
#define NSTAGE 4
#define SMEM_TOTAL (NSTAGE * ST_BYTES)   // 81920 (epilogue 67584B reused inside)

// ---------------- device scratch (static, allocation-free) ----------------
__device__ int   g_counts[NE];
__device__ int   g_tok[NE * NTOK];
__device__ int   g_off[NE];
__device__ int   g_mtile_e[MAXMT];
__device__ int   g_num_mtiles;
__device__ int   g_total_rows;
__device__ int   g_texp[NTOK * 2];
__device__ int   g_tslot[NTOK * 2];
__device__ float g_tcoef[NTOK * 2];

__device__ __align__(16) __half X_h[(size_t)MAXROWS * HDIM];
__device__ __align__(16) __half WT_h[(size_t)NE * HDIM * HDIM];
__device__ __align__(16) float  Y[(size_t)MAXROWS * HDIM];

// ---------------- PTX helpers ----------------
__device__ __forceinline__ uint32_t smem_u32(const void* p) {
    uint32_t a;
    asm("{ .reg .u64 t; cvta.to.shared.u64 t, %1; cvt.u32.u64 %0, t; }" : "=r"(a) : "l"(p));
    return a;
}
__device__ __forceinline__ void cp16(uint32_t dst, const void* src) {
    asm volatile("cp.async.cg.shared.global [%0], [%1], 16;" :: "r"(dst), "l"(src));
}
#define CP_COMMIT() asm volatile("cp.async.commit_group;" ::: "memory")
#define CP_WAIT(n)  asm volatile("cp.async.wait_group %0;" :: "n"(n) : "memory")

__device__ __forceinline__ void ldm_x4(uint32_t* r, uint32_t addr) {
    asm volatile("ldmatrix.sync.aligned.m8n8.x4.shared.b16 {%0,%1,%2,%3}, [%4];"
                 : "=r"(r[0]), "=r"(r[1]), "=r"(r[2]), "=r"(r[3]) : "r"(addr));
}
__device__ __forceinline__ void mma_fp16(float* d, const uint32_t* a, const uint32_t* b) {
    asm volatile("mma.sync.aligned.m16n8k16.row.col.f32.f16.f16.f32 "
                 "{%0,%1,%2,%3}, {%4,%5,%6,%7}, {%8,%9}, {%0,%1,%2,%3};"
                 : "+f"(d[0]), "+f"(d[1]), "+f"(d[2]), "+f"(d[3])
                 : "r"(a[0]), "r"(a[1]), "r"(a[2]), "r"(a[3]), "r"(b[0]), "r"(b[1]));
}

// ---------------- kernels ----------------
__global__ void zero_counts_kernel() {
    if (threadIdx.x < NE) g_counts[threadIdx.x] = 0;
}

__global__ void router_kernel(const float* __restrict__ tokens,
                              const float* __restrict__ rw,
                              const float* __restrict__ rb) {
    __shared__ float sw[NE * HDIM];
    int tid = threadIdx.x;
    for (int i = tid; i < NE * HDIM; i += blockDim.x) sw[i] = rw[i];
    __syncthreads();

    int warp = tid >> 5, lane = tid & 31;
    int token = blockIdx.x * 8 + warp;
    if (token >= NTOK) return;

    const float* x = tokens + (size_t)token * HDIM;
    float acc[NE];
#pragma unroll
    for (int e = 0; e < NE; e++) acc[e] = 0.f;
    for (int i = lane; i < HDIM; i += 32) {
        float xv = x[i];
#pragma unroll
        for (int e = 0; e < NE; e++) acc[e] += xv * sw[e * HDIM + i];
    }
#pragma unroll
    for (int off = 16; off > 0; off >>= 1)
#pragma unroll
        for (int e = 0; e < NE; e++) acc[e] += __shfl_xor_sync(0xffffffffu, acc[e], off);

    if (lane == 0) {
        float lg[NE];
#pragma unroll
        for (int e = 0; e < NE; e++) lg[e] = acc[e] + rb[e];
        float mx = lg[0];
#pragma unroll
        for (int e = 1; e < NE; e++) mx = fmaxf(mx, lg[e]);
        float p[NE], Z = 0.f;
#pragma unroll
        for (int e = 0; e < NE; e++) { p[e] = expf(lg[e] - mx); Z += p[e]; }
#pragma unroll
        for (int e = 0; e < NE; e++) p[e] /= Z;

        int i0 = 0;
#pragma unroll
        for (int e = 1; e < NE; e++) if (p[e] > p[i0]) i0 = e;
        int i1 = (i0 == 0) ? 1 : 0;
#pragma unroll
        for (int e = 0; e < NE; e++) if (e != i0 && p[e] > p[i1]) i1 = e;

        float p0 = p[i0], p1 = p[i1];
        float s = p0 + p1;
        float w0 = p0 / (s + EPSI), w1 = p1 / (s + EPSI);
        float swsum = w0 + w1;
        float accw = fmaxf(swsum, EPSI);
        float scale = 1.f + swsum * EPSI;
        float c0 = w0 / accw * scale, c1 = w1 / accw * scale;

        int s0 = atomicAdd(&g_counts[i0], 1);
        g_tok[i0 * NTOK + s0] = token;
        g_texp[token * 2 + 0] = i0; g_tslot[token * 2 + 0] = s0; g_tcoef[token * 2 + 0] = c0;
        int s1 = atomicAdd(&g_counts[i1], 1);
        g_tok[i1 * NTOK + s1] = token;
        g_texp[token * 2 + 1] = i1; g_tslot[token * 2 + 1] = s1; g_tcoef[token * 2 + 1] = c1;
    }
}

__global__ void offsets_kernel() {
    if (threadIdx.x != 0) return;
    int off = 0, mti = 0;
    for (int e = 0; e < NE; e++) {
        g_off[e] = off;
        int cp = ((g_counts[e] + BM - 1) / BM) * BM;
        for (int t = 0; t < cp / BM; t++) g_mtile_e[mti++] = e;
        off += cp;
    }
    g_total_rows = off;
    g_num_mtiles = mti;
}

// gather + fp32->fp16 conversion of token rows into dense per-expert X
__global__ void gather_kernel(const float* __restrict__ tokens) {
    int row = blockIdx.x;
    if (row >= g_total_rows) return;
    int e = 0;
#pragma unroll
    for (int i = 1; i < NE; i++) if (row >= g_off[i]) e = i;
    int slot = row - g_off[e];
    int tid = threadIdx.x;                 // 128 threads, 8 elems each
    size_t dst = (size_t)row * HDIM + tid * 8;

    __align__(16) __half h[8];
    if (slot < g_counts[e]) {
        int tok = g_tok[e * NTOK + slot];
        const float4* s = reinterpret_cast<const float4*>(&tokens[(size_t)tok * HDIM + tid * 8]);
        float4 a = s[0], b = s[1];
        h[0] = __float2half_rn(a.x); h[1] = __float2half_rn(a.y);
        h[2] = __float2half_rn(a.z); h[3] = __float2half_rn(a.w);
        h[4] = __float2half_rn(b.x); h[5] = __float2half_rn(b.y);
        h[6] = __float2half_rn(b.z); h[7] = __float2half_rn(b.w);
    } else {
#pragma unroll
        for (int i = 0; i < 8; i++) h[i] = __float2half_rn(0.f);
    }
    *reinterpret_cast<uint4*>(&X_h[dst]) = *reinterpret_cast<const uint4*>(h);
}

// transpose expert weights [E][K][N] -> [E][N][K] fp16
__global__ void wtrans_kernel(const float* __restrict__ ew) {
    __shared__ float t[32][33];
    int e = blockIdx.z, kt = blockIdx.x, nt = blockIdx.y;
    int tx = threadIdx.x, ty = threadIdx.y;   // 32 x 8
    const float* src = ew + ((size_t)e * HDIM + kt * 32) * HDIM + nt * 32;
#pragma unroll
    for (int i = 0; i < 4; i++)
        t[ty + i * 8][tx] = src[(size_t)(ty + i * 8) * HDIM + tx];
    __syncthreads();
    size_t dbase = ((size_t)e * HDIM + nt * 32) * HDIM + kt * 32;
#pragma unroll
    for (int i = 0; i < 4; i++)
        WT_h[dbase + (size_t)(ty + i * 8) * HDIM + tx] = __float2half_rn(t[tx][ty + i * 8]);
}

// ---------------- HMMA grouped GEMM: Y[rows, :] = X @ W_e^T --------------
// 128x128 tile, 8 warps (2x4), warp tile 64x32, pure fp16 single pass,
// 4-stage cp.async pipeline.
__global__ void __launch_bounds__(256, 2) moe_gemm_mma() {
    extern __shared__ __align__(16) char smem[];
    int mt = blockIdx.x >> 3;      // NTILES = 8
    int nt = blockIdx.x & 7;
    if (mt >= g_num_mtiles) return;
    int e = g_mtile_e[mt];
    int row_base = mt * BM;
    int col_base = nt * BN;

    uint32_t sb = smem_u32(smem);
    int tid = threadIdx.x, wid = tid >> 5, lane = tid & 31;
    int wm = wid >> 2, wn = wid & 3;              // warp tile: rows wm*64, cols wn*32
    int g = lane >> 2, tg = lane & 3;

    const size_t wbase = ((size_t)e * HDIM + col_base) * HDIM;

    auto load_stage = [&](int c, int s) {
        uint32_t st = sb + s * ST_BYTES;
        int k0 = c * BK;
        // each sub-tile: 128 rows x 32 fp16 (64B = 4 x 16B chunks)
#pragma unroll
        for (int j = 0; j < 2; j++) {
            int u = tid + j * 256;
            int r = u >> 2, cc = (u & 3) << 4;    // byte offset within row
            uint32_t off = (uint32_t)(r * (ROWST * 2)) + cc;
            size_t soA = (size_t)(row_base + r) * HDIM + k0 + (cc >> 1);
            size_t soB = wbase + (size_t)r * HDIM + k0 + (cc >> 1);
            cp16(st + SM_A + off, &X_h[soA]);
            cp16(st + SM_B + off, &WT_h[soB]);
        }
        CP_COMMIT();
    };

    float acc[4][4][4];
#pragma unroll
    for (int i = 0; i < 4; i++)
#pragma unroll
        for (int j = 0; j < 4; j++)
#pragma unroll
            for (int q = 0; q < 4; q++) acc[i][j][q] = 0.f;

    load_stage(0, 0);
    load_stage(1, 1);
    load_stage(2, 2);

    // ldmatrix lane address components (element units in a [128][ROWST] tile)
    int a_row = wm * 64 + (lane & 15);            // + mi*16
    int a_colsel = (lane >> 4) * 8;               // 0 or 8
    int b_row = wn * 32 + (lane & 7) + ((lane >> 4) << 3);   // + nb*16
    int b_colsel = ((lane >> 3) & 1) * 8;

    const int NIT = HDIM / BK;                    // 32
    int s = 0;
    for (int c = 0; c < NIT; c++) {
        CP_WAIT(2);
        __syncthreads();
        uint32_t st = sb + s * ST_BYTES;

#pragma unroll
        for (int kk = 0; kk < BK; kk += 16) {
            uint32_t bh[2][4];
#pragma unroll
            for (int nb = 0; nb < 2; nb++) {      // each x4 covers two n8 tiles
                uint32_t boff = (uint32_t)((b_row + nb * 16) * (ROWST * 2) + (kk + b_colsel) * 2);
                ldm_x4(bh[nb], st + SM_B + boff);
            }
#pragma unroll
            for (int mi = 0; mi < 4; mi++) {
                uint32_t ah[4];
                uint32_t aoff = (uint32_t)((a_row + mi * 16) * (ROWST * 2) + (kk + a_colsel) * 2);
                ldm_x4(ah, st + SM_A + aoff);
#pragma unroll
                for (int ni = 0; ni < 4; ni++)
                    mma_fp16(acc[mi][ni], ah, &bh[ni >> 1][(ni & 1) * 2]);
            }
        }
        __syncthreads();
        if (c + NSTAGE - 1 < NIT) load_stage(c + NSTAGE - 1, (s + NSTAGE - 1) % NSTAGE);
        else CP_COMMIT();                         // empty group keeps pending-count invariant
        s = (s == NSTAGE - 1) ? 0 : s + 1;
    }

    // ---- epilogue: stage accumulators in SMEM (reuse stages), coalesced out
    float* s_out = reinterpret_cast<float*>(smem);   // [128][132] = 67584B < 81920B
#pragma unroll
    for (int mi = 0; mi < 4; mi++)
#pragma unroll
        for (int ni = 0; ni < 4; ni++) {
            int r0 = wm * 64 + mi * 16 + g;
            int cc = wn * 32 + ni * 8 + tg * 2;
            *reinterpret_cast<float2*>(&s_out[r0 * 132 + cc]) =
                make_float2(acc[mi][ni][0], acc[mi][ni][1]);
            *reinterpret_cast<float2*>(&s_out[(r0 + 8) * 132 + cc]) =
                make_float2(acc[mi][ni][2], acc[mi][ni][3]);
        }
    __syncthreads();

#pragma unroll
    for (int i = 0; i < 16; i++) {
        int u = tid + i * 256;                    // 4096 float4 slots
        int r = u >> 5, cc = (u & 31) << 2;
        float4 v = *reinterpret_cast<const float4*>(&s_out[r * 132 + cc]);
        *reinterpret_cast<float4*>(&Y[(size_t)(row_base + r) * HDIM + col_base + cc]) = v;
    }
}

// combine: out[t] = c0 * Y[row0] + c1 * Y[row1]
__global__ void combine_kernel(float* __restrict__ out) {
    int t = blockIdx.x;
    int e0 = g_texp[2 * t], e1 = g_texp[2 * t + 1];
    size_t r0 = (size_t)(g_off[e0] + g_tslot[2 * t]);
    size_t r1 = (size_t)(g_off[e1] + g_tslot[2 * t + 1]);
    float c0 = g_tcoef[2 * t], c1 = g_tcoef[2 * t + 1];
    int i = threadIdx.x * 4;
    float4 y0 = *reinterpret_cast<const float4*>(&Y[r0 * HDIM + i]);
    float4 y1 = *reinterpret_cast<const float4*>(&Y[r1 * HDIM + i]);
    float4 o;
    o.x = c0 * y0.x + c1 * y1.x;
    o.y = c0 * y0.y + c1 * y1.y;
    o.z = c0 * y0.z + c1 * y1.z;
    o.w = c0 * y0.w + c1 * y1.w;
    *reinterpret_cast<float4*>(&out[(size_t)t * HDIM + i]) = o;
}

// ---------------- launch ----------------
extern "C" void kernel_launch(void* const* d_in, const int* in_sizes, int n_in,
                              void* d_out, int out_size) {
    const float* tokens = (const float*)d_in[0];   // [4,2048,1024]
    const float* rw     = (const float*)d_in[1];   // [8,1024]
    const float* rb     = (const float*)d_in[2];   // [8]
    const float* ew     = (const float*)d_in[3];   // [8,1024,1024]
    float* out = (float*)d_out;

    cudaFuncSetAttribute(moe_gemm_mma, cudaFuncAttributeMaxDynamicSharedMemorySize, SMEM_TOTAL);

    zero_counts_kernel<<<1, 32>>>();
    wtrans_kernel<<<dim3(32, 32, 8), dim3(32, 8)>>>(ew);
    router_kernel<<<NTOK / 8, 256>>>(tokens, rw, rb);
    offsets_kernel<<<1, 32>>>();
    gather_kernel<<<MAXROWS, 128>>>(tokens);
    moe_gemm_mma<<<MAXMT * NTILES, 256, SMEM_TOTAL>>>();
    combine_kernel<<<NTOK, 256>>>(out);
    (void)in_sizes; (void)n_in; (void)out_size;
}

// round 6
// speedup vs baseline: 3.6925x; 1.0890x over previous
#include <cuda_runtime.h>
#include <cuda_fp16.h>
#include <cstdint>

// Problem constants (B=4, S=2048, H=1024, E=8, TOP_K=2)
#define NE    8
#define NTOK  8192
#define HDIM  1024
#define EPSI  1e-10f

// GEMM tiling
#define BM 128
#define BN 128
#define BK 32
#define NTILES (HDIM / BN)          // 8
#define MAXMT  (NTOK * 2 / BM + NE) // 136

// SMEM: 4 stages; per stage A/B each 128 rows x 40 fp16 (80B stride)
#define ROWST 40
#define TILE_B (128 * ROWST * 2)    // 10240 bytes per sub-tile
#define ST_BYTES (2 * TILE_B)       // 20480
#define SM_A 0
#define SM_B TILE_B
#define NSTAGE 4
#define SMEM_TOTAL (NSTAGE * ST_BYTES)   // 81920 (epilogue 67584B reused inside)

// ---------------- device scratch (static, allocation-free) ----------------
__device__ int   g_counts[NE];
__device__ int   g_texp[NTOK * 2];
__device__ int   g_tslot[NTOK * 2];
__device__ float g_tcoef[NTOK * 2];

// fixed-capacity per-expert regions: row = e * NTOK + slot
__device__ __align__(16) __half X_h[(size_t)NE * NTOK * HDIM];
__device__ __align__(16) __half WT_h[(size_t)NE * HDIM * HDIM];
__device__ __align__(16) float  Y[(size_t)NE * NTOK * HDIM];

// ---------------- PTX helpers ----------------
__device__ __forceinline__ uint32_t smem_u32(const void* p) {
    uint32_t a;
    asm("{ .reg .u64 t; cvta.to.shared.u64 t, %1; cvt.u32.u64 %0, t; }" : "=r"(a) : "l"(p));
    return a;
}
__device__ __forceinline__ void cp16(uint32_t dst, const void* src) {
    asm volatile("cp.async.cg.shared.global [%0], [%1], 16;" :: "r"(dst), "l"(src));
}
// zero-fill variant: src_size=0 -> writes 16 zero bytes, no global read
__device__ __forceinline__ void cp16z(uint32_t dst, const void* src, uint32_t src_size) {
    asm volatile("cp.async.cg.shared.global [%0], [%1], 16, %2;"
                 :: "r"(dst), "l"(src), "r"(src_size));
}
#define CP_COMMIT() asm volatile("cp.async.commit_group;" ::: "memory")
#define CP_WAIT(n)  asm volatile("cp.async.wait_group %0;" :: "n"(n) : "memory")

__device__ __forceinline__ void ldm_x4(uint32_t* r, uint32_t addr) {
    asm volatile("ldmatrix.sync.aligned.m8n8.x4.shared.b16 {%0,%1,%2,%3}, [%4];"
                 : "=r"(r[0]), "=r"(r[1]), "=r"(r[2]), "=r"(r[3]) : "r"(addr));
}
__device__ __forceinline__ void mma_fp16(float* d, const uint32_t* a, const uint32_t* b) {
    asm volatile("mma.sync.aligned.m16n8k16.row.col.f32.f16.f16.f32 "
                 "{%0,%1,%2,%3}, {%4,%5,%6,%7}, {%8,%9}, {%0,%1,%2,%3};"
                 : "+f"(d[0]), "+f"(d[1]), "+f"(d[2]), "+f"(d[3])
                 : "r"(a[0]), "r"(a[1]), "r"(a[2]), "r"(a[3]), "r"(b[0]), "r"(b[1]));
}

// ---------------- kernels ----------------
// transpose expert weights [E][K][N] -> [E][N][K] fp16; block (0,0,0) zeroes counts
__global__ void wtrans_kernel(const float* __restrict__ ew) {
    __shared__ float t[32][33];
    int e = blockIdx.z, kt = blockIdx.x, nt = blockIdx.y;
    int tx = threadIdx.x, ty = threadIdx.y;   // 32 x 8
    if (e == 0 && kt == 0 && nt == 0 && ty == 0 && tx < NE) g_counts[tx] = 0;
    const float* src = ew + ((size_t)e * HDIM + kt * 32) * HDIM + nt * 32;
#pragma unroll
    for (int i = 0; i < 4; i++)
        t[ty + i * 8][tx] = src[(size_t)(ty + i * 8) * HDIM + tx];
    __syncthreads();
    size_t dbase = ((size_t)e * HDIM + nt * 32) * HDIM + kt * 32;
#pragma unroll
    for (int i = 0; i < 4; i++)
        WT_h[dbase + (size_t)(ty + i * 8) * HDIM + tx] = __float2half_rn(t[tx][ty + i * 8]);
}

__global__ void router_kernel(const float* __restrict__ tokens,
                              const float* __restrict__ rw,
                              const float* __restrict__ rb) {
    __shared__ float sw[NE * HDIM];
    int tid = threadIdx.x;
    for (int i = tid; i < NE * HDIM; i += blockDim.x) sw[i] = rw[i];
    __syncthreads();

    int warp = tid >> 5, lane = tid & 31;
    int token = blockIdx.x * 8 + warp;
    if (token >= NTOK) return;

    const float* x = tokens + (size_t)token * HDIM;
    float acc[NE];
#pragma unroll
    for (int e = 0; e < NE; e++) acc[e] = 0.f;
    for (int i = lane; i < HDIM; i += 32) {
        float xv = x[i];
#pragma unroll
        for (int e = 0; e < NE; e++) acc[e] += xv * sw[e * HDIM + i];
    }
#pragma unroll
    for (int off = 16; off > 0; off >>= 1)
#pragma unroll
        for (int e = 0; e < NE; e++) acc[e] += __shfl_xor_sync(0xffffffffu, acc[e], off);

    if (lane == 0) {
        float lg[NE];
#pragma unroll
        for (int e = 0; e < NE; e++) lg[e] = acc[e] + rb[e];
        float mx = lg[0];
#pragma unroll
        for (int e = 1; e < NE; e++) mx = fmaxf(mx, lg[e]);
        float p[NE], Z = 0.f;
#pragma unroll
        for (int e = 0; e < NE; e++) { p[e] = expf(lg[e] - mx); Z += p[e]; }
#pragma unroll
        for (int e = 0; e < NE; e++) p[e] /= Z;

        int i0 = 0;
#pragma unroll
        for (int e = 1; e < NE; e++) if (p[e] > p[i0]) i0 = e;
        int i1 = (i0 == 0) ? 1 : 0;
#pragma unroll
        for (int e = 0; e < NE; e++) if (e != i0 && p[e] > p[i1]) i1 = e;

        float p0 = p[i0], p1 = p[i1];
        float s = p0 + p1;
        float w0 = p0 / (s + EPSI), w1 = p1 / (s + EPSI);
        float swsum = w0 + w1;
        float accw = fmaxf(swsum, EPSI);
        float scale = 1.f + swsum * EPSI;
        float c0 = w0 / accw * scale, c1 = w1 / accw * scale;

        int s0 = atomicAdd(&g_counts[i0], 1);
        g_texp[token * 2 + 0] = i0; g_tslot[token * 2 + 0] = s0; g_tcoef[token * 2 + 0] = c0;
        int s1 = atomicAdd(&g_counts[i1], 1);
        g_texp[token * 2 + 1] = i1; g_tslot[token * 2 + 1] = s1; g_tcoef[token * 2 + 1] = c1;
    }
}

// gather: one block per assignment; X row = e*NTOK + slot
__global__ void gather_kernel(const float* __restrict__ tokens) {
    int a = blockIdx.x;                    // 0 .. NTOK*2-1
    int token = a >> 1;
    int e = g_texp[a], slot = g_tslot[a];
    int tid = threadIdx.x;                 // 128 threads, 8 elems each
    size_t dst = ((size_t)e * NTOK + slot) * HDIM + tid * 8;

    const float4* s = reinterpret_cast<const float4*>(&tokens[(size_t)token * HDIM + tid * 8]);
    float4 va = s[0], vb = s[1];
    __align__(16) __half h[8];
    h[0] = __float2half_rn(va.x); h[1] = __float2half_rn(va.y);
    h[2] = __float2half_rn(va.z); h[3] = __float2half_rn(va.w);
    h[4] = __float2half_rn(vb.x); h[5] = __float2half_rn(vb.y);
    h[6] = __float2half_rn(vb.z); h[7] = __float2half_rn(vb.w);
    *reinterpret_cast<uint4*>(&X_h[dst]) = *reinterpret_cast<const uint4*>(h);
}

// ---------------- HMMA grouped GEMM: Y[e*NTOK+slot, :] = X @ W_e^T ----------
// 128x128 tile, 8 warps (2x4), warp tile 64x32, pure fp16 single pass,
// 4-stage cp.async pipeline, one barrier per K-iter, eager loads, zfill pads.
__global__ void __launch_bounds__(256, 2) moe_gemm_mma() {
    extern __shared__ __align__(16) char smem[];

    // map blockIdx -> (expert, m_tile, n_tile) from runtime counts
    int bid = blockIdx.x;
    int e = -1, cnt = 0;
#pragma unroll
    for (int ee = 0; ee < NE; ee++) {
        int c = g_counts[ee];
        int t = ((c + BM - 1) / BM) * NTILES;
        if (e < 0) {
            if (bid < t) { e = ee; cnt = c; }
            else bid -= t;
        }
    }
    if (e < 0) return;
    int nt = bid & (NTILES - 1);
    int mt = bid / NTILES;
    int row_base = mt * BM;                   // slot base within expert e
    int col_base = nt * BN;

    uint32_t sb = smem_u32(smem);
    int tid = threadIdx.x, wid = tid >> 5, lane = tid & 31;
    int wm = wid >> 2, wn = wid & 3;
    int g = lane >> 2, tg = lane & 3;

    const size_t abase = (size_t)e * NTOK * HDIM;
    const size_t wbase = ((size_t)e * HDIM + col_base) * HDIM;

    // per-thread A-load row validity (same rows every stage)
    int lr0 = (tid >> 2), lr1 = (tid >> 2) + 64;       // rows for j=0,1
    uint32_t sz0 = (row_base + lr0 < cnt) ? 16u : 0u;
    uint32_t sz1 = (row_base + lr1 < cnt) ? 16u : 0u;
    int ar0 = sz0 ? (row_base + lr0) : 0;              // clamp addr for safety
    int ar1 = sz1 ? (row_base + lr1) : 0;

    auto load_stage = [&](int c, int s) {
        uint32_t st = sb + s * ST_BYTES;
        int k0 = c * BK;
        int cc = (tid & 3) << 4;                       // byte offset within row
        {   // j = 0: rows 0..63
            uint32_t off = (uint32_t)(lr0 * (ROWST * 2)) + cc;
            cp16z(st + SM_A + off, &X_h[abase + (size_t)ar0 * HDIM + k0 + (cc >> 1)], sz0);
            cp16(st + SM_B + off, &WT_h[wbase + (size_t)lr0 * HDIM + k0 + (cc >> 1)]);
        }
        {   // j = 1: rows 64..127
            uint32_t off = (uint32_t)(lr1 * (ROWST * 2)) + cc;
            cp16z(st + SM_A + off, &X_h[abase + (size_t)ar1 * HDIM + k0 + (cc >> 1)], sz1);
            cp16(st + SM_B + off, &WT_h[wbase + (size_t)lr1 * HDIM + k0 + (cc >> 1)]);
        }
        CP_COMMIT();
    };

    float acc[4][4][4];
#pragma unroll
    for (int i = 0; i < 4; i++)
#pragma unroll
        for (int j = 0; j < 4; j++)
#pragma unroll
            for (int q = 0; q < 4; q++) acc[i][j][q] = 0.f;

    load_stage(0, 0);
    load_stage(1, 1);
    load_stage(2, 2);

    int a_row = wm * 64 + (lane & 15);
    int a_colsel = (lane >> 4) * 8;
    int b_row = wn * 32 + (lane & 7) + ((lane >> 4) << 3);
    int b_colsel = ((lane >> 3) & 1) * 8;

    const int NIT = HDIM / BK;                // 32
    for (int c = 0; c < NIT; c++) {
        int s = c & (NSTAGE - 1);
        CP_WAIT(2);
        __syncthreads();
        // eager: issue next stage load before compute (overwrites stage read
        // at iter c-1; the barrier above orders it)
        if (c + NSTAGE - 1 < NIT) load_stage(c + NSTAGE - 1, (c + NSTAGE - 1) & (NSTAGE - 1));
        else CP_COMMIT();

        uint32_t st = sb + s * ST_BYTES;
#pragma unroll
        for (int kk = 0; kk < BK; kk += 16) {
            uint32_t bh[2][4];
#pragma unroll
            for (int nb = 0; nb < 2; nb++) {
                uint32_t boff = (uint32_t)((b_row + nb * 16) * (ROWST * 2) + (kk + b_colsel) * 2);
                ldm_x4(bh[nb], st + SM_B + boff);
            }
#pragma unroll
            for (int mi = 0; mi < 4; mi++) {
                uint32_t ah[4];
                uint32_t aoff = (uint32_t)((a_row + mi * 16) * (ROWST * 2) + (kk + a_colsel) * 2);
                ldm_x4(ah, st + SM_A + aoff);
#pragma unroll
                for (int ni = 0; ni < 4; ni++)
                    mma_fp16(acc[mi][ni], ah, &bh[ni >> 1][(ni & 1) * 2]);
            }
        }
    }
    __syncthreads();   // all reads done before epilogue reuses smem

    // ---- epilogue: stage accumulators in SMEM, coalesced out
    float* s_out = reinterpret_cast<float*>(smem);   // [128][132]
#pragma unroll
    for (int mi = 0; mi < 4; mi++)
#pragma unroll
        for (int ni = 0; ni < 4; ni++) {
            int r0 = wm * 64 + mi * 16 + g;
            int cc = wn * 32 + ni * 8 + tg * 2;
            *reinterpret_cast<float2*>(&s_out[r0 * 132 + cc]) =
                make_float2(acc[mi][ni][0], acc[mi][ni][1]);
            *reinterpret_cast<float2*>(&s_out[(r0 + 8) * 132 + cc]) =
                make_float2(acc[mi][ni][2], acc[mi][ni][3]);
        }
    __syncthreads();

#pragma unroll
    for (int i = 0; i < 16; i++) {
        int u = tid + i * 256;
        int r = u >> 5, cc = (u & 31) << 2;
        float4 v = *reinterpret_cast<const float4*>(&s_out[r * 132 + cc]);
        *reinterpret_cast<float4*>(
            &Y[(abase + (size_t)(row_base + r) * HDIM) + col_base + cc]) = v;
    }
}

// combine: out[t] = c0 * Y[e0*NTOK+s0] + c1 * Y[e1*NTOK+s1]
__global__ void combine_kernel(float* __restrict__ out) {
    int t = blockIdx.x;
    int a0 = 2 * t, a1 = 2 * t + 1;
    size_t r0 = (size_t)g_texp[a0] * NTOK + g_tslot[a0];
    size_t r1 = (size_t)g_texp[a1] * NTOK + g_tslot[a1];
    float c0 = g_tcoef[a0], c1 = g_tcoef[a1];
    int i = threadIdx.x * 4;
    float4 y0 = *reinterpret_cast<const float4*>(&Y[r0 * HDIM + i]);
    float4 y1 = *reinterpret_cast<const float4*>(&Y[r1 * HDIM + i]);
    float4 o;
    o.x = c0 * y0.x + c1 * y1.x;
    o.y = c0 * y0.y + c1 * y1.y;
    o.z = c0 * y0.z + c1 * y1.z;
    o.w = c0 * y0.w + c1 * y1.w;
    *reinterpret_cast<float4*>(&out[(size_t)t * HDIM + i]) = o;
}

// ---------------- launch ----------------
extern "C" void kernel_launch(void* const* d_in, const int* in_sizes, int n_in,
                              void* d_out, int out_size) {
    const float* tokens = (const float*)d_in[0];   // [4,2048,1024]
    const float* rw     = (const float*)d_in[1];   // [8,1024]
    const float* rb     = (const float*)d_in[2];   // [8]
    const float* ew     = (const float*)d_in[3];   // [8,1024,1024]
    float* out = (float*)d_out;

    cudaFuncSetAttribute(moe_gemm_mma, cudaFuncAttributeMaxDynamicSharedMemorySize, SMEM_TOTAL);

    wtrans_kernel<<<dim3(32, 32, 8), dim3(32, 8)>>>(ew);   // also zeroes g_counts
    router_kernel<<<NTOK / 8, 256>>>(tokens, rw, rb);
    gather_kernel<<<NTOK * 2, 128>>>(tokens);
    moe_gemm_mma<<<MAXMT * NTILES, 256, SMEM_TOTAL>>>();
    combine_kernel<<<NTOK, 256>>>(out);
    (void)in_sizes; (void)n_in; (void)out_size;
}